// round 14
// baseline (speedup 1.0000x reference)
#include <cuda_runtime.h>
#include <cuda_bf16.h>
#include <cstdint>
#include <stdint.h>
#include <math.h>

// Problem constants
constexpr int BB  = 2;
constexpr int TT  = 2048;
constexpr int CC  = 2048;
constexpr int HH  = 16;
constexpr int HKVV = 4;
constexpr int DD  = 128;
constexpr int RR  = 64;
constexpr int KVC = HKVV * DD;      // 512
constexpr int REP = HH / HKVV;      // 4
constexpr int MROWS = BB * TT;      // 4096

// ---------------------------------------------------------------------------
// Scratch (static __device__ arrays; no allocations allowed)
// ---------------------------------------------------------------------------
__device__ float g_q[(size_t)MROWS * CC];
__device__ float g_k[(size_t)MROWS * KVC];
__device__ float g_v[(size_t)MROWS * KVC];
__device__ float g_y[(size_t)MROWS * CC];
__device__ float g_s[(size_t)BB * HH * TT * TT];        // e stash
__device__ unsigned int g_qh[(size_t)MROWS * CC / 2];   // roped q bf16 hi pairs
__device__ unsigned int g_ql[(size_t)MROWS * CC / 2];
__device__ unsigned int g_kh[(size_t)MROWS * KVC / 2];
__device__ unsigned int g_kl[(size_t)MROWS * KVC / 2];
__device__ unsigned int g_xh[(size_t)MROWS * CC / 2];   // x bf16 hi pairs [M][K/2]
__device__ unsigned int g_xl[(size_t)MROWS * CC / 2];
__device__ unsigned int g_wqh[(size_t)CC * CC / 2];     // Wq^T packed [N][K/2]
__device__ unsigned int g_wql[(size_t)CC * CC / 2];
__device__ unsigned int g_wkh[(size_t)KVC * CC / 2];    // Wk^T packed [N][K/2]
__device__ unsigned int g_wkl[(size_t)KVC * CC / 2];

// ---------------------------------------------------------------------------
// helpers
// ---------------------------------------------------------------------------
__device__ __forceinline__ unsigned int f2tf(float f) {
    unsigned int r;
    asm("cvt.rna.tf32.f32 %0, %1;" : "=r"(r) : "f"(f));
    return r;
}

__device__ __forceinline__ void split_bf16x2(float f0, float f1,
                                             unsigned int& hi, unsigned int& lo) {
    __nv_bfloat162 h = __floats2bfloat162_rn(f0, f1);
    float2 hf = __bfloat1622float2(h);
    __nv_bfloat162 l = __floats2bfloat162_rn(f0 - hf.x, f1 - hf.y);
    hi = *reinterpret_cast<unsigned int*>(&h);
    lo = *reinterpret_cast<unsigned int*>(&l);
}

__device__ __forceinline__ void cp16(void* smem_ptr, const void* gptr) {
    unsigned int s = (unsigned int)__cvta_generic_to_shared(smem_ptr);
    asm volatile("cp.async.cg.shared.global [%0], [%1], 16;" :: "r"(s), "l"(gptr));
}

__device__ __forceinline__ void mma_tf32(float* d, const unsigned int* a, const unsigned int* b) {
    asm volatile(
        "mma.sync.aligned.m16n8k8.row.col.f32.tf32.tf32.f32 "
        "{%0,%1,%2,%3}, {%4,%5,%6,%7}, {%8,%9}, {%0,%1,%2,%3};"
        : "+f"(d[0]), "+f"(d[1]), "+f"(d[2]), "+f"(d[3])
        : "r"(a[0]), "r"(a[1]), "r"(a[2]), "r"(a[3]), "r"(b[0]), "r"(b[1]));
}

__device__ __forceinline__ void mma_bf16(float* d, const unsigned int* a, const unsigned int* b) {
    asm volatile(
        "mma.sync.aligned.m16n8k16.row.col.f32.bf16.bf16.f32 "
        "{%0,%1,%2,%3}, {%4,%5,%6,%7}, {%8,%9}, {%0,%1,%2,%3};"
        : "+f"(d[0]), "+f"(d[1]), "+f"(d[2]), "+f"(d[3])
        : "r"(a[0]), "r"(a[1]), "r"(a[2]), "r"(a[3]), "r"(b[0]), "r"(b[1]));
}

// ---------------------------------------------------------------------------
// Pre-split kernels
// ---------------------------------------------------------------------------
__global__ void xsplit_kernel(const float* __restrict__ X,
                              unsigned int* __restrict__ Xh,
                              unsigned int* __restrict__ Xl, int total)
{
    int i = blockIdx.x * blockDim.x + threadIdx.x;
    if (i >= total) return;
    unsigned int hi, lo;
    split_bf16x2(X[2 * (size_t)i], X[2 * (size_t)i + 1], hi, lo);
    Xh[i] = hi;
    Xl[i] = lo;
}

// W [K=2048][N] row-major -> Wt hi/lo packed [N][K/2] (transpose + split)
__global__ __launch_bounds__(256) void wsplit_kernel(
    const float* __restrict__ W,
    unsigned int* __restrict__ Th, unsigned int* __restrict__ Tl, int N)
{
    __shared__ float t[64][65];
    const int k0 = blockIdx.x * 64, n0 = blockIdx.y * 64;
    const int tid = threadIdx.x;
    const int KU = CC / 2;
    for (int i = tid; i < 64 * 64; i += 256) {
        int r = i >> 6, c = i & 63;
        t[r][c] = W[(size_t)(k0 + r) * N + n0 + c];
    }
    __syncthreads();
    for (int i = tid; i < 64 * 32; i += 256) {
        int n = i >> 5, kp = i & 31;
        unsigned int hi, lo;
        split_bf16x2(t[2 * kp][n], t[2 * kp + 1][n], hi, lo);
        size_t o = (size_t)(n0 + n) * KU + (k0 >> 1) + kp;
        Th[o] = hi;
        Tl[o] = lo;
    }
}

// ---------------------------------------------------------------------------
// Packed bf16x2 3-term GEMM: C[M,N] = A[M,K] @ Wt[N,K]^T, fp32 out.
// Operands pre-split: Ah/Al [M][K/2], Bh/Bl [N][K/2] packed bf16x2.
// Block 128x128, BK=16 (8 uints), 8 warps (2x4), warp tile 64x32.
// smem pitch 12 uints -> all fragment loads conflict-free.
// Mainloop = pure LDS + MMA (no CVT, no split).
// ---------------------------------------------------------------------------
constexpr int GP = 12;                 // uint pitch
constexpr int G_STAGE = 128 * GP;      // uints per array per stage

__global__ __launch_bounds__(256, 1) void tgemm3p_kernel(
    int M, int N, int K,
    const unsigned int* __restrict__ Ah, const unsigned int* __restrict__ Al,
    const unsigned int* __restrict__ Bh, const unsigned int* __restrict__ Bl,
    float* __restrict__ C)
{
    __shared__ unsigned int us[2 * 4 * G_STAGE];   // 49152 B

    const int tid  = threadIdx.x;
    const int lane = tid & 31;
    const int w    = tid >> 5;
    const int wm   = w >> 2;
    const int wn   = w & 3;
    const int grp  = lane >> 2;
    const int qid  = lane & 3;

    const size_t bm = (size_t)blockIdx.y * 128;
    const size_t bn = (size_t)blockIdx.x * 128;
    const int KU = K >> 1;

    float acc[4][4][4];
    #pragma unroll
    for (int i = 0; i < 4; ++i)
        #pragma unroll
        for (int j = 0; j < 4; ++j)
            #pragma unroll
            for (int c = 0; c < 4; ++c) acc[i][j][c] = 0.0f;

    const unsigned int* srcs[4] = {Ah, Al, Bh, Bl};
    const int row  = tid >> 1;
    const int half = tid & 1;

    auto load_stage = [&](int ku0, int buf) {
        #pragma unroll
        for (int t = 0; t < 4; ++t) {
            const size_t row0 = (t < 2) ? bm : bn;
            unsigned int* dst = us + (buf * 4 + t) * G_STAGE;
            cp16(&dst[row * GP + half * 4],
                 srcs[t] + (row0 + row) * KU + ku0 + half * 4);
        }
        asm volatile("cp.async.commit_group;");
    };

    load_stage(0, 0);

    const int nst = K / 16;
    for (int s = 0; s < nst; ++s) {
        asm volatile("cp.async.wait_group 0;");
        __syncthreads();
        if (s + 1 < nst) load_stage((s + 1) * 8, (s + 1) & 1);

        const unsigned int* base = us + (s & 1) * 4 * G_STAGE;
        const unsigned int* Ahs = base;
        const unsigned int* Als = base + G_STAGE;
        const unsigned int* Bhs = base + 2 * G_STAGE;
        const unsigned int* Bls = base + 3 * G_STAGE;

        unsigned int ah[4][4], al[4][4], bh[4][2], bl[4][2];
        #pragma unroll
        for (int mt = 0; mt < 4; ++mt) {
            int r0 = wm * 64 + mt * 16 + grp;
            ah[mt][0] = Ahs[r0 * GP + qid];
            ah[mt][1] = Ahs[(r0 + 8) * GP + qid];
            ah[mt][2] = Ahs[r0 * GP + qid + 4];
            ah[mt][3] = Ahs[(r0 + 8) * GP + qid + 4];
            al[mt][0] = Als[r0 * GP + qid];
            al[mt][1] = Als[(r0 + 8) * GP + qid];
            al[mt][2] = Als[r0 * GP + qid + 4];
            al[mt][3] = Als[(r0 + 8) * GP + qid + 4];
        }
        #pragma unroll
        for (int nt = 0; nt < 4; ++nt) {
            int cc = wn * 32 + nt * 8 + grp;
            bh[nt][0] = Bhs[cc * GP + qid];
            bh[nt][1] = Bhs[cc * GP + qid + 4];
            bl[nt][0] = Bls[cc * GP + qid];
            bl[nt][1] = Bls[cc * GP + qid + 4];
        }
        #pragma unroll
        for (int mt = 0; mt < 4; ++mt)
            #pragma unroll
            for (int nt = 0; nt < 4; ++nt) {
                mma_bf16(acc[mt][nt], al[mt], bh[nt]);   // lo*hi
                mma_bf16(acc[mt][nt], ah[mt], bl[nt]);   // hi*lo
                mma_bf16(acc[mt][nt], ah[mt], bh[nt]);   // hi*hi
            }
        __syncthreads();
    }

    #pragma unroll
    for (int mt = 0; mt < 4; ++mt) {
        #pragma unroll
        for (int nt = 0; nt < 4; ++nt) {
            size_t r  = bm + wm * 64 + mt * 16 + grp;
            size_t c0 = bn + wn * 32 + nt * 8 + 2 * qid;
            *(float2*)&C[r * (size_t)N + c0]       = make_float2(acc[mt][nt][0], acc[mt][nt][1]);
            *(float2*)&C[(r + 8) * (size_t)N + c0] = make_float2(acc[mt][nt][2], acc[mt][nt][3]);
        }
    }
}

// ---------------------------------------------------------------------------
// tf32 mma.sync GEMM (single tf32 — smooth paths Wv/Wo)
// ---------------------------------------------------------------------------
__global__ __launch_bounds__(256) void tgemm1_kernel(
    int M, int N, int K,
    const float* __restrict__ A, const float* __restrict__ B,
    float* __restrict__ C)
{
    constexpr int BM = 128, BN = 128, BK = 16, AP = 20, BP = 136;
    __shared__ float As[2][BM * AP];
    __shared__ float Bs[2][BK * BP];

    const int tid  = threadIdx.x;
    const int lane = tid & 31;
    const int w    = tid >> 5;
    const int wm   = w >> 2;
    const int wn   = w & 3;
    const int grp  = lane >> 2;
    const int qid  = lane & 3;

    const size_t bm = (size_t)blockIdx.y * BM;
    const size_t bn = (size_t)blockIdx.x * BN;

    float acc[4][4][4];
    #pragma unroll
    for (int i = 0; i < 4; ++i)
        #pragma unroll
        for (int j = 0; j < 4; ++j)
            #pragma unroll
            for (int c = 0; c < 4; ++c) acc[i][j][c] = 0.0f;

    auto load_stage = [&](int k0, int buf) {
        #pragma unroll
        for (int c = 0; c < 2; ++c) {
            int idx = tid + c * 256;
            int row = idx >> 2, col = (idx & 3) * 4;
            cp16(&As[buf][row * AP + col], &A[(bm + row) * (size_t)K + k0 + col]);
        }
        #pragma unroll
        for (int c = 0; c < 2; ++c) {
            int idx = tid + c * 256;
            int row = idx >> 5, col = (idx & 31) * 4;
            cp16(&Bs[buf][row * BP + col], &B[(size_t)(k0 + row) * N + bn + col]);
        }
    };

    load_stage(0, 0);
    asm volatile("cp.async.commit_group;");

    const int nst = K / BK;
    for (int s = 0; s < nst; ++s) {
        asm volatile("cp.async.wait_group 0;");
        __syncthreads();
        const int cur = s & 1;
        if (s + 1 < nst) {
            load_stage((s + 1) * BK, cur ^ 1);
            asm volatile("cp.async.commit_group;");
        }
        const float* Asb = As[cur];
        const float* Bsb = Bs[cur];
        #pragma unroll
        for (int ks = 0; ks < BK; ks += 8) {
            unsigned int af[4][4], bf[4][2];
            #pragma unroll
            for (int mt = 0; mt < 4; ++mt) {
                int r0 = wm * 64 + mt * 16 + grp;
                af[mt][0] = f2tf(Asb[r0 * AP + ks + qid]);
                af[mt][1] = f2tf(Asb[(r0 + 8) * AP + ks + qid]);
                af[mt][2] = f2tf(Asb[r0 * AP + ks + qid + 4]);
                af[mt][3] = f2tf(Asb[(r0 + 8) * AP + ks + qid + 4]);
            }
            #pragma unroll
            for (int nt = 0; nt < 4; ++nt) {
                int c0 = wn * 32 + nt * 8 + grp;
                bf[nt][0] = f2tf(Bsb[(ks + qid) * BP + c0]);
                bf[nt][1] = f2tf(Bsb[(ks + qid + 4) * BP + c0]);
            }
            #pragma unroll
            for (int mt = 0; mt < 4; ++mt)
                #pragma unroll
                for (int nt = 0; nt < 4; ++nt)
                    mma_tf32(acc[mt][nt], af[mt], bf[nt]);
        }
        __syncthreads();
    }

    #pragma unroll
    for (int mt = 0; mt < 4; ++mt) {
        #pragma unroll
        for (int nt = 0; nt < 4; ++nt) {
            size_t r  = bm + wm * 64 + mt * 16 + grp;
            size_t c0 = bn + wn * 32 + nt * 8 + 2 * qid;
            *(float2*)&C[r * (size_t)N + c0]       = make_float2(acc[mt][nt][0], acc[mt][nt][1]);
            *(float2*)&C[(r + 8) * (size_t)N + c0] = make_float2(acc[mt][nt][2], acc[mt][nt][3]);
        }
    }
}

// ---------------------------------------------------------------------------
// Fused RoPE + bf16 hi/lo split+pack
// ---------------------------------------------------------------------------
__global__ void rope_split_kernel(const float* __restrict__ src,
                                  unsigned int* __restrict__ dsth,
                                  unsigned int* __restrict__ dstl,
                                  const float* __restrict__ cosb,
                                  const float* __restrict__ sinb,
                                  int nh, int pitch, int total)
{
    int idx = blockIdx.x * blockDim.x + threadIdx.x;
    if (idx >= total) return;
    int cp  = idx & 63;
    int h   = (idx >> 6) % nh;
    int row = idx / (64 * nh);
    int t   = row % TT;

    const float* p = src + (size_t)row * pitch + h * DD;

    float f[2];
    #pragma unroll
    for (int i = 0; i < 2; ++i) {
        int d = 2 * cp + i;
        float x = p[d];
        if (d < 32)
            f[i] = x * cosb[t * RR + d] - p[d + 32] * sinb[t * RR + d];
        else if (d < 64)
            f[i] = x * cosb[t * RR + d] + p[d - 32] * sinb[t * RR + d];
        else
            f[i] = x;
    }
    unsigned int hi, lo;
    split_bf16x2(f[0], f[1], hi, lo);
    size_t o = (size_t)row * (pitch / 2) + h * 64 + cp;
    dsth[o] = hi;
    dstl[o] = lo;
}

// ---------------------------------------------------------------------------
// Two-pass causal attention with threshold gating.
// Pass 1: QK bf16x2 3-term MMA; e into smem; conditional e-stash write
//         (skip tiles already provably below gate threshold).
// Pass 2: exact tile-skip, gate, PV via tf32 MMA.
// ---------------------------------------------------------------------------
constexpr int BQ  = 64;
constexpr int BKT = 64;
constexpr int KP  = 68;
constexpr int SP  = 65;
constexpr int VPITCH = 136;
constexpr int PPITCH = 68;
constexpr int RDP = 17;
constexpr int NKT = TT / BKT;
constexpr int ATT_SMEM_FLOATS =
    4 * BQ * KP + BQ * SP + BQ * VPITCH + BQ * PPITCH + BQ * RDP
    + 2 * NKT * BQ + 4 * BQ + 4;
constexpr int ATT_SMEM_BYTES = ATT_SMEM_FLOATS * 4;

__global__ __launch_bounds__(256, 1) void attn_kernel(
    const float* __restrict__ Vm, const float* __restrict__ gate,
    float* __restrict__ Y)
{
    extern __shared__ float sm[];
    unsigned int* Qhu = (unsigned int*)sm;
    unsigned int* Qlu = Qhu + BQ * KP;
    unsigned int* Khu = Qlu + BQ * KP;
    unsigned int* Klu = Khu + BQ * KP;
    float* Ss       = (float*)(Klu + BQ * KP);
    float* Vs       = Ss + BQ * SP;
    float* Ps       = Vs + BQ * VPITCH;
    float* red      = Ps + BQ * PPITCH;
    float* mn_all   = red + BQ * RDP;
    float* tmax_all = mn_all + NKT * BQ;
    float* m_s      = tmax_all + NKT * BQ;
    float* l_s      = m_s + BQ;
    float* mn_s     = l_s + BQ;
    float* li_s     = mn_s + BQ;
    float* sflag    = li_s + BQ;
    unsigned int* Vsu = (unsigned int*)Vs;
    unsigned int* Psu = (unsigned int*)Ps;

    const int qt = blockIdx.x;
    const int bh = blockIdx.y;
    const int b  = bh / HH;
    const int h  = bh % HH;
    const int q0 = qt * BQ;
    const int tid  = threadIdx.x;
    const int ty   = tid / 16;
    const int tx   = tid % 16;
    const int lane = tid & 31;
    const int w    = tid >> 5;
    const int wm   = w >> 2;
    const int wn   = w & 3;
    const int grp  = lane >> 2;
    const int qid  = lane & 3;

    const float scale = 0.08838834764831845f;
    const float thr = 1.0f / (1.0f + __expf(-gate[h]));

    const unsigned int* Qhg = g_qh + (size_t)(b * TT) * (CC / 2) + h * 64;
    const unsigned int* Qlg = g_ql + (size_t)(b * TT) * (CC / 2) + h * 64;
    const unsigned int* Khg = g_kh + (size_t)(b * TT) * (KVC / 2) + (h / REP) * 64;
    const unsigned int* Klg = g_kl + (size_t)(b * TT) * (KVC / 2) + (h / REP) * 64;
    const float* Vb = Vm + (size_t)(b * TT) * KVC + (h / REP) * DD;
    float* Eb = g_s + ((size_t)bh * TT + q0) * TT;

    for (int e = tid; e < BQ * 64; e += 256) {
        int r = e >> 6, cp = e & 63;
        Qhu[r * KP + cp] = Qhg[(size_t)(q0 + r) * (CC / 2) + cp];
        Qlu[r * KP + cp] = Qlg[(size_t)(q0 + r) * (CC / 2) + cp];
    }
    if (tid < BQ) { m_s[tid] = -1e30f; l_s[tid] = 0.0f; }
    __syncthreads();

    const int m0  = wm * 32;
    const int n0q = wn * 16;

    // ---------------- PASS 1 ----------------
    for (int kt = 0; kt <= qt; ++kt) {
        const int s0 = kt * BKT;

        for (int e = tid; e < BKT * 64; e += 256) {
            int r = e >> 6, cp = e & 63;
            Khu[r * KP + cp] = Khg[(size_t)(s0 + r) * (KVC / 2) + cp];
            Klu[r * KP + cp] = Klg[(size_t)(s0 + r) * (KVC / 2) + cp];
        }
        __syncthreads();

        float sacc[2][2][4];
        #pragma unroll
        for (int mt = 0; mt < 2; ++mt)
            #pragma unroll
            for (int nt = 0; nt < 2; ++nt)
                #pragma unroll
                for (int c = 0; c < 4; ++c) sacc[mt][nt][c] = 0.0f;

        #pragma unroll
        for (int ks = 0; ks < 8; ++ks) {
            const int kp0 = ks * 8;
            unsigned int ah[2][4], al[2][4], bh[2][2], bl[2][2];
            #pragma unroll
            for (int mt = 0; mt < 2; ++mt) {
                int rr = m0 + mt * 16 + grp;
                ah[mt][0] = Qhu[rr * KP + kp0 + qid];
                ah[mt][1] = Qhu[(rr + 8) * KP + kp0 + qid];
                ah[mt][2] = Qhu[rr * KP + kp0 + qid + 4];
                ah[mt][3] = Qhu[(rr + 8) * KP + kp0 + qid + 4];
                al[mt][0] = Qlu[rr * KP + kp0 + qid];
                al[mt][1] = Qlu[(rr + 8) * KP + kp0 + qid];
                al[mt][2] = Qlu[rr * KP + kp0 + qid + 4];
                al[mt][3] = Qlu[(rr + 8) * KP + kp0 + qid + 4];
            }
            #pragma unroll
            for (int nt = 0; nt < 2; ++nt) {
                int cc = n0q + nt * 8 + grp;
                bh[nt][0] = Khu[cc * KP + kp0 + qid];
                bh[nt][1] = Khu[cc * KP + kp0 + qid + 4];
                bl[nt][0] = Klu[cc * KP + kp0 + qid];
                bl[nt][1] = Klu[cc * KP + kp0 + qid + 4];
            }
            #pragma unroll
            for (int mt = 0; mt < 2; ++mt)
                #pragma unroll
                for (int nt = 0; nt < 2; ++nt) {
                    mma_bf16(sacc[mt][nt], al[mt], bh[nt]);
                    mma_bf16(sacc[mt][nt], ah[mt], bl[nt]);
                    mma_bf16(sacc[mt][nt], ah[mt], bh[nt]);
                }
        }

        const bool diag = (kt == qt);
        #pragma unroll
        for (int mt = 0; mt < 2; ++mt) {
            #pragma unroll
            for (int nt = 0; nt < 2; ++nt) {
                int rr = m0 + mt * 16 + grp;
                int cc = n0q + nt * 8 + 2 * qid;
                float v0 = sacc[mt][nt][0] * scale;
                float v1 = sacc[mt][nt][1] * scale;
                float v2 = sacc[mt][nt][2] * scale;
                float v3 = sacc[mt][nt][3] * scale;
                if (diag) {
                    if (cc > rr)         v0 = -1e30f;
                    if (cc + 1 > rr)     v1 = -1e30f;
                    if (cc > rr + 8)     v2 = -1e30f;
                    if (cc + 1 > rr + 8) v3 = -1e30f;
                }
                Ss[rr * SP + cc]           = v0;
                Ss[rr * SP + cc + 1]       = v1;
                Ss[(rr + 8) * SP + cc]     = v2;
                Ss[(rr + 8) * SP + cc + 1] = v3;
            }
        }
        __syncthreads();

        #pragma unroll
        for (int i = 0; i < 4; ++i) {
            const int r = ty + 16 * i;
            float pm = -1e30f;
            #pragma unroll
            for (int j = 0; j < 4; ++j)
                pm = fmaxf(pm, Ss[r * SP + tx + 16 * j]);
            red[r * RDP + tx] = pm;
        }
        __syncthreads();

        float mo = 0.0f, mn = 0.0f;
        if (tid < BQ) {
            float tm = red[tid * RDP];
            #pragma unroll
            for (int k = 1; k < 16; ++k) tm = fmaxf(tm, red[tid * RDP + k]);
            mo = m_s[tid];
            mn = fmaxf(mo, tm);
            mn_s[tid] = mn;
            mn_all[kt * BQ + tid] = mn;
            tmax_all[kt * BQ + tid] = tm;
        }
        if (tid == 0) sflag[0] = 0.0f;
        __syncthreads();

        // e = exp(s - mn) written in place into Ss + partial row sums
        #pragma unroll
        for (int i = 0; i < 4; ++i) {
            const int r = ty + 16 * i;
            const float mr = mn_s[r];
            float ps = 0.0f;
            #pragma unroll
            for (int j = 0; j < 4; ++j) {
                const int c = tx + 16 * j;
                float ei = __expf(Ss[r * SP + c] - mr);
                Ss[r * SP + c] = ei;
                ps += ei;
            }
            red[r * RDP + tx] = ps;
        }
        __syncthreads();

        if (tid < BQ) {
            float ts = 0.0f;
            #pragma unroll
            for (int k = 0; k < 16; ++k) ts += red[tid * RDP + k];
            float ln = l_s[tid] * __expf(mo - mn) + ts;
            l_s[tid] = ln;
            m_s[tid] = mn;
            // early-dead test (conservative: m and l only grow)
            float etm = __expf(tmax_all[kt * BQ + tid] - mn);
            if (etm * 1.00001f >= thr * ln) sflag[0] = 1.0f;
        }
        __syncthreads();

        if (sflag[0] != 0.0f) {
            for (int e = tid; e < BQ * BKT; e += 256) {
                int r = e >> 6, c = e & 63;
                Eb[(size_t)r * TT + s0 + c] = Ss[r * SP + c];
            }
        }
        // next-iteration K load + its sync orders these reads before Ss reuse
    }

    if (tid < BQ) li_s[tid] = 1.0f / l_s[tid];
    __syncthreads();

    // ---------------- PASS 2: tile-skip + gate + PV ----------------
    float o[2][4][4];
    #pragma unroll
    for (int mt = 0; mt < 2; ++mt)
        #pragma unroll
        for (int nt = 0; nt < 4; ++nt)
            #pragma unroll
            for (int c = 0; c < 4; ++c) o[mt][nt][c] = 0.0f;

    const int n0 = wn * 32;

    for (int kt = 0; kt <= qt; ++kt) {
        const int s0 = kt * BKT;

        if (tid == 0) sflag[0] = 0.0f;
        __syncthreads();
        if (tid < BQ) {
            float pmax = __expf(tmax_all[kt * BQ + tid] - m_s[tid]) * li_s[tid];
            mn_s[tid] = __expf(mn_all[kt * BQ + tid] - m_s[tid]) * li_s[tid];
            if (pmax * 1.00001f >= thr) sflag[0] = 1.0f;
        }
        __syncthreads();
        if (sflag[0] == 0.0f) continue;

        for (int e = tid; e < BKT * DD; e += 256) {
            int r = e >> 7, d = e & 127;
            Vsu[r * VPITCH + d] = f2tf(Vb[(size_t)(s0 + r) * KVC + d]);
        }
        __syncthreads();

        for (int e = tid; e < BQ * BKT; e += 256) {
            int r = e >> 6, c = e & 63;
            float p = Eb[(size_t)r * TT + s0 + c] * mn_s[r];
            if (p < thr) p = 0.0f;
            Psu[r * PPITCH + c] = f2tf(p);
        }
        __syncthreads();

        #pragma unroll
        for (int k = 0; k < BKT; k += 8) {
            unsigned int af[2][4], bf[4][2];
            #pragma unroll
            for (int mt = 0; mt < 2; ++mt) {
                int rr = m0 + mt * 16 + grp;
                af[mt][0] = Psu[rr * PPITCH + k + qid];
                af[mt][1] = Psu[(rr + 8) * PPITCH + k + qid];
                af[mt][2] = Psu[rr * PPITCH + k + qid + 4];
                af[mt][3] = Psu[(rr + 8) * PPITCH + k + qid + 4];
            }
            #pragma unroll
            for (int nt = 0; nt < 4; ++nt) {
                int cc = n0 + nt * 8 + grp;
                bf[nt][0] = Vsu[(k + qid) * VPITCH + cc];
                bf[nt][1] = Vsu[(k + qid + 4) * VPITCH + cc];
            }
            #pragma unroll
            for (int mt = 0; mt < 2; ++mt)
                #pragma unroll
                for (int nt = 0; nt < 4; ++nt)
                    mma_tf32(o[mt][nt], af[mt], bf[nt]);
        }
        __syncthreads();
    }

    #pragma unroll
    for (int mt = 0; mt < 2; ++mt) {
        #pragma unroll
        for (int nt = 0; nt < 4; ++nt) {
            size_t row = (size_t)(b * TT + q0 + m0 + mt * 16 + grp);
            size_t col = h * DD + n0 + nt * 8 + 2 * qid;
            *(float2*)&Y[row * CC + col]       = make_float2(o[mt][nt][0], o[mt][nt][1]);
            *(float2*)&Y[(row + 8) * CC + col] = make_float2(o[mt][nt][2], o[mt][nt][3]);
        }
    }
}

// ---------------------------------------------------------------------------
// Launch
// ---------------------------------------------------------------------------
extern "C" void kernel_launch(void* const* d_in, const int* in_sizes, int n_in,
                              void* d_out, int out_size)
{
    const float* x    = (const float*)d_in[0];
    const float* cosb = (const float*)d_in[1];
    const float* sinb = (const float*)d_in[2];
    const float* Wq   = (const float*)d_in[3];
    const float* Wk   = (const float*)d_in[4];
    const float* Wv   = (const float*)d_in[5];
    const float* Wo   = (const float*)d_in[6];
    const float* gate = (const float*)d_in[7];
    float* out = (float*)d_out;

    float *q, *k, *v, *y;
    unsigned int *qh, *ql, *kh, *kl, *xh, *xl, *wqh, *wql, *wkh, *wkl;
    cudaGetSymbolAddress((void**)&q,   g_q);
    cudaGetSymbolAddress((void**)&k,   g_k);
    cudaGetSymbolAddress((void**)&v,   g_v);
    cudaGetSymbolAddress((void**)&y,   g_y);
    cudaGetSymbolAddress((void**)&qh,  g_qh);
    cudaGetSymbolAddress((void**)&ql,  g_ql);
    cudaGetSymbolAddress((void**)&kh,  g_kh);
    cudaGetSymbolAddress((void**)&kl,  g_kl);
    cudaGetSymbolAddress((void**)&xh,  g_xh);
    cudaGetSymbolAddress((void**)&xl,  g_xl);
    cudaGetSymbolAddress((void**)&wqh, g_wqh);
    cudaGetSymbolAddress((void**)&wql, g_wql);
    cudaGetSymbolAddress((void**)&wkh, g_wkh);
    cudaGetSymbolAddress((void**)&wkl, g_wkl);

    static bool attr_set = false;
    if (!attr_set) {
        cudaFuncSetAttribute(attn_kernel,
                             cudaFuncAttributeMaxDynamicSharedMemorySize, ATT_SMEM_BYTES);
        attr_set = true;
    }

    // Pre-split operands
    {
        int totx = MROWS * (CC / 2);
        xsplit_kernel<<<(totx + 255) / 256, 256>>>(x, xh, xl, totx);
        wsplit_kernel<<<dim3(CC / 64, CC / 64), 256>>>(Wq, wqh, wql, CC);
        wsplit_kernel<<<dim3(CC / 64, KVC / 64), 256>>>(Wk, wkh, wkl, KVC);
    }

    // q/k projections: packed bf16x2 3-term (gate-critical precision)
    tgemm3p_kernel<<<dim3(CC / 128, MROWS / 128), 256>>>(MROWS, CC,  CC, xh, xl, wqh, wql, q);
    tgemm3p_kernel<<<dim3(KVC / 128, MROWS / 128), 256>>>(MROWS, KVC, CC, xh, xl, wkh, wkl, k);

    // v projection (smooth -> single tf32)
    tgemm1_kernel<<<dim3(KVC / 128, MROWS / 128), 256>>>(MROWS, KVC, CC, x, Wv, v);

    // Fused RoPE + bf16 split for attention q/k
    {
        int totq = MROWS * HH * 64;
        int totk = MROWS * HKVV * 64;
        rope_split_kernel<<<(totq + 255) / 256, 256>>>(q, qh, ql, cosb, sinb, HH, CC, totq);
        rope_split_kernel<<<(totk + 255) / 256, 256>>>(k, kh, kl, cosb, sinb, HKVV, KVC, totk);
    }

    // Attention
    attn_kernel<<<dim3(TT / BQ, BB * HH), 256, ATT_SMEM_BYTES>>>(v, gate, y);

    // Output projection (smooth -> single tf32)
    tgemm1_kernel<<<dim3(CC / 128, MROWS / 128), 256>>>(MROWS, CC, CC, y, Wo, out);
}

// round 15
// speedup vs baseline: 1.0523x; 1.0523x over previous
#include <cuda_runtime.h>
#include <cuda_bf16.h>
#include <cstdint>
#include <stdint.h>
#include <math.h>

// Problem constants
constexpr int BB  = 2;
constexpr int TT  = 2048;
constexpr int CC  = 2048;
constexpr int HH  = 16;
constexpr int HKVV = 4;
constexpr int DD  = 128;
constexpr int RR  = 64;
constexpr int KVC = HKVV * DD;      // 512
constexpr int REP = HH / HKVV;      // 4
constexpr int MROWS = BB * TT;      // 4096

// ---------------------------------------------------------------------------
// Scratch (static __device__ arrays; no allocations allowed)
// ---------------------------------------------------------------------------
__device__ float g_q[(size_t)MROWS * CC];
__device__ float g_k[(size_t)MROWS * KVC];
__device__ float g_v[(size_t)MROWS * KVC];
__device__ float g_y[(size_t)MROWS * CC];
__device__ float g_s[(size_t)BB * HH * TT * TT];        // e stash
__device__ unsigned int g_qh[(size_t)MROWS * CC / 2];   // roped q bf16 hi pairs
__device__ unsigned int g_ql[(size_t)MROWS * CC / 2];
__device__ unsigned int g_kh[(size_t)MROWS * KVC / 2];
__device__ unsigned int g_kl[(size_t)MROWS * KVC / 2];
__device__ unsigned int g_xh[(size_t)MROWS * CC / 2];   // x bf16 hi pairs [M][K/2]
__device__ unsigned int g_xl[(size_t)MROWS * CC / 2];
__device__ unsigned int g_wqh[(size_t)CC * CC / 2];     // Wq^T packed [N][K/2]
__device__ unsigned int g_wql[(size_t)CC * CC / 2];
__device__ unsigned int g_wkh[(size_t)KVC * CC / 2];    // Wk^T packed [N][K/2]
__device__ unsigned int g_wkl[(size_t)KVC * CC / 2];

// ---------------------------------------------------------------------------
// helpers
// ---------------------------------------------------------------------------
__device__ __forceinline__ unsigned int f2tf(float f) {
    unsigned int r;
    asm("cvt.rna.tf32.f32 %0, %1;" : "=r"(r) : "f"(f));
    return r;
}

__device__ __forceinline__ void split_bf16x2(float f0, float f1,
                                             unsigned int& hi, unsigned int& lo) {
    __nv_bfloat162 h = __floats2bfloat162_rn(f0, f1);
    float2 hf = __bfloat1622float2(h);
    __nv_bfloat162 l = __floats2bfloat162_rn(f0 - hf.x, f1 - hf.y);
    hi = *reinterpret_cast<unsigned int*>(&h);
    lo = *reinterpret_cast<unsigned int*>(&l);
}

__device__ __forceinline__ void cp16(void* smem_ptr, const void* gptr) {
    unsigned int s = (unsigned int)__cvta_generic_to_shared(smem_ptr);
    asm volatile("cp.async.cg.shared.global [%0], [%1], 16;" :: "r"(s), "l"(gptr));
}

__device__ __forceinline__ void mma_tf32(float* d, const unsigned int* a, const unsigned int* b) {
    asm volatile(
        "mma.sync.aligned.m16n8k8.row.col.f32.tf32.tf32.f32 "
        "{%0,%1,%2,%3}, {%4,%5,%6,%7}, {%8,%9}, {%0,%1,%2,%3};"
        : "+f"(d[0]), "+f"(d[1]), "+f"(d[2]), "+f"(d[3])
        : "r"(a[0]), "r"(a[1]), "r"(a[2]), "r"(a[3]), "r"(b[0]), "r"(b[1]));
}

__device__ __forceinline__ void mma_bf16(float* d, const unsigned int* a, const unsigned int* b) {
    asm volatile(
        "mma.sync.aligned.m16n8k16.row.col.f32.bf16.bf16.f32 "
        "{%0,%1,%2,%3}, {%4,%5,%6,%7}, {%8,%9}, {%0,%1,%2,%3};"
        : "+f"(d[0]), "+f"(d[1]), "+f"(d[2]), "+f"(d[3])
        : "r"(a[0]), "r"(a[1]), "r"(a[2]), "r"(a[3]), "r"(b[0]), "r"(b[1]));
}

// ---------------------------------------------------------------------------
// Pre-split kernels
// ---------------------------------------------------------------------------
__global__ void xsplit_kernel(const float* __restrict__ X,
                              unsigned int* __restrict__ Xh,
                              unsigned int* __restrict__ Xl, int total)
{
    int i = blockIdx.x * blockDim.x + threadIdx.x;
    if (i >= total) return;
    unsigned int hi, lo;
    split_bf16x2(X[2 * (size_t)i], X[2 * (size_t)i + 1], hi, lo);
    Xh[i] = hi;
    Xl[i] = lo;
}

// W [K=2048][N] row-major -> Wt hi/lo packed [N][K/2] (transpose + split)
__global__ __launch_bounds__(256) void wsplit_kernel(
    const float* __restrict__ W,
    unsigned int* __restrict__ Th, unsigned int* __restrict__ Tl, int N)
{
    __shared__ float t[64][65];
    const int k0 = blockIdx.x * 64, n0 = blockIdx.y * 64;
    const int tid = threadIdx.x;
    const int KU = CC / 2;
    for (int i = tid; i < 64 * 64; i += 256) {
        int r = i >> 6, c = i & 63;
        t[r][c] = W[(size_t)(k0 + r) * N + n0 + c];
    }
    __syncthreads();
    for (int i = tid; i < 64 * 32; i += 256) {
        int n = i >> 5, kp = i & 31;
        unsigned int hi, lo;
        split_bf16x2(t[2 * kp][n], t[2 * kp + 1][n], hi, lo);
        size_t o = (size_t)(n0 + n) * KU + (k0 >> 1) + kp;
        Th[o] = hi;
        Tl[o] = lo;
    }
}

// ---------------------------------------------------------------------------
// Packed bf16x2 3-term GEMM (term-major MMA order to break acc RAW chains).
// ---------------------------------------------------------------------------
constexpr int GP = 12;                 // uint pitch
constexpr int G_STAGE = 128 * GP;      // uints per array per stage

__global__ __launch_bounds__(256, 1) void tgemm3p_kernel(
    int M, int N, int K,
    const unsigned int* __restrict__ Ah, const unsigned int* __restrict__ Al,
    const unsigned int* __restrict__ Bh, const unsigned int* __restrict__ Bl,
    float* __restrict__ C)
{
    __shared__ unsigned int us[2 * 4 * G_STAGE];   // 49152 B

    const int tid  = threadIdx.x;
    const int lane = tid & 31;
    const int w    = tid >> 5;
    const int wm   = w >> 2;
    const int wn   = w & 3;
    const int grp  = lane >> 2;
    const int qid  = lane & 3;

    const size_t bm = (size_t)blockIdx.y * 128;
    const size_t bn = (size_t)blockIdx.x * 128;
    const int KU = K >> 1;

    float acc[4][4][4];
    #pragma unroll
    for (int i = 0; i < 4; ++i)
        #pragma unroll
        for (int j = 0; j < 4; ++j)
            #pragma unroll
            for (int c = 0; c < 4; ++c) acc[i][j][c] = 0.0f;

    const unsigned int* srcs[4] = {Ah, Al, Bh, Bl};
    const int row  = tid >> 1;
    const int half = tid & 1;

    auto load_stage = [&](int ku0, int buf) {
        #pragma unroll
        for (int t = 0; t < 4; ++t) {
            const size_t row0 = (t < 2) ? bm : bn;
            unsigned int* dst = us + (buf * 4 + t) * G_STAGE;
            cp16(&dst[row * GP + half * 4],
                 srcs[t] + (row0 + row) * KU + ku0 + half * 4);
        }
        asm volatile("cp.async.commit_group;");
    };

    load_stage(0, 0);

    const int nst = K / 16;
    for (int s = 0; s < nst; ++s) {
        asm volatile("cp.async.wait_group 0;");
        __syncthreads();
        if (s + 1 < nst) load_stage((s + 1) * 8, (s + 1) & 1);

        const unsigned int* base = us + (s & 1) * 4 * G_STAGE;
        const unsigned int* Ahs = base;
        const unsigned int* Als = base + G_STAGE;
        const unsigned int* Bhs = base + 2 * G_STAGE;
        const unsigned int* Bls = base + 3 * G_STAGE;

        unsigned int ah[4][4], al[4][4], bh[4][2], bl[4][2];
        #pragma unroll
        for (int mt = 0; mt < 4; ++mt) {
            int r0 = wm * 64 + mt * 16 + grp;
            ah[mt][0] = Ahs[r0 * GP + qid];
            ah[mt][1] = Ahs[(r0 + 8) * GP + qid];
            ah[mt][2] = Ahs[r0 * GP + qid + 4];
            ah[mt][3] = Ahs[(r0 + 8) * GP + qid + 4];
            al[mt][0] = Als[r0 * GP + qid];
            al[mt][1] = Als[(r0 + 8) * GP + qid];
            al[mt][2] = Als[r0 * GP + qid + 4];
            al[mt][3] = Als[(r0 + 8) * GP + qid + 4];
        }
        #pragma unroll
        for (int nt = 0; nt < 4; ++nt) {
            int cc = wn * 32 + nt * 8 + grp;
            bh[nt][0] = Bhs[cc * GP + qid];
            bh[nt][1] = Bhs[cc * GP + qid + 4];
            bl[nt][0] = Bls[cc * GP + qid];
            bl[nt][1] = Bls[cc * GP + qid + 4];
        }
        // term-major: same-acc reuse distance = 16 MMAs (hides HMMA latency)
        #pragma unroll
        for (int mt = 0; mt < 4; ++mt)
            #pragma unroll
            for (int nt = 0; nt < 4; ++nt)
                mma_bf16(acc[mt][nt], al[mt], bh[nt]);
        #pragma unroll
        for (int mt = 0; mt < 4; ++mt)
            #pragma unroll
            for (int nt = 0; nt < 4; ++nt)
                mma_bf16(acc[mt][nt], ah[mt], bl[nt]);
        #pragma unroll
        for (int mt = 0; mt < 4; ++mt)
            #pragma unroll
            for (int nt = 0; nt < 4; ++nt)
                mma_bf16(acc[mt][nt], ah[mt], bh[nt]);
        __syncthreads();
    }

    #pragma unroll
    for (int mt = 0; mt < 4; ++mt) {
        #pragma unroll
        for (int nt = 0; nt < 4; ++nt) {
            size_t r  = bm + wm * 64 + mt * 16 + grp;
            size_t c0 = bn + wn * 32 + nt * 8 + 2 * qid;
            *(float2*)&C[r * (size_t)N + c0]       = make_float2(acc[mt][nt][0], acc[mt][nt][1]);
            *(float2*)&C[(r + 8) * (size_t)N + c0] = make_float2(acc[mt][nt][2], acc[mt][nt][3]);
        }
    }
}

// ---------------------------------------------------------------------------
// tf32 mma.sync GEMM (single tf32 — smooth paths Wv/Wo)
// ---------------------------------------------------------------------------
__global__ __launch_bounds__(256) void tgemm1_kernel(
    int M, int N, int K,
    const float* __restrict__ A, const float* __restrict__ B,
    float* __restrict__ C)
{
    constexpr int BM = 128, BN = 128, BK = 16, AP = 20, BP = 136;
    __shared__ float As[2][BM * AP];
    __shared__ float Bs[2][BK * BP];

    const int tid  = threadIdx.x;
    const int lane = tid & 31;
    const int w    = tid >> 5;
    const int wm   = w >> 2;
    const int wn   = w & 3;
    const int grp  = lane >> 2;
    const int qid  = lane & 3;

    const size_t bm = (size_t)blockIdx.y * BM;
    const size_t bn = (size_t)blockIdx.x * BN;

    float acc[4][4][4];
    #pragma unroll
    for (int i = 0; i < 4; ++i)
        #pragma unroll
        for (int j = 0; j < 4; ++j)
            #pragma unroll
            for (int c = 0; c < 4; ++c) acc[i][j][c] = 0.0f;

    auto load_stage = [&](int k0, int buf) {
        #pragma unroll
        for (int c = 0; c < 2; ++c) {
            int idx = tid + c * 256;
            int row = idx >> 2, col = (idx & 3) * 4;
            cp16(&As[buf][row * AP + col], &A[(bm + row) * (size_t)K + k0 + col]);
        }
        #pragma unroll
        for (int c = 0; c < 2; ++c) {
            int idx = tid + c * 256;
            int row = idx >> 5, col = (idx & 31) * 4;
            cp16(&Bs[buf][row * BP + col], &B[(size_t)(k0 + row) * N + bn + col]);
        }
    };

    load_stage(0, 0);
    asm volatile("cp.async.commit_group;");

    const int nst = K / BK;
    for (int s = 0; s < nst; ++s) {
        asm volatile("cp.async.wait_group 0;");
        __syncthreads();
        const int cur = s & 1;
        if (s + 1 < nst) {
            load_stage((s + 1) * BK, cur ^ 1);
            asm volatile("cp.async.commit_group;");
        }
        const float* Asb = As[cur];
        const float* Bsb = Bs[cur];
        #pragma unroll
        for (int ks = 0; ks < BK; ks += 8) {
            unsigned int af[4][4], bf[4][2];
            #pragma unroll
            for (int mt = 0; mt < 4; ++mt) {
                int r0 = wm * 64 + mt * 16 + grp;
                af[mt][0] = f2tf(Asb[r0 * AP + ks + qid]);
                af[mt][1] = f2tf(Asb[(r0 + 8) * AP + ks + qid]);
                af[mt][2] = f2tf(Asb[r0 * AP + ks + qid + 4]);
                af[mt][3] = f2tf(Asb[(r0 + 8) * AP + ks + qid + 4]);
            }
            #pragma unroll
            for (int nt = 0; nt < 4; ++nt) {
                int c0 = wn * 32 + nt * 8 + grp;
                bf[nt][0] = f2tf(Bsb[(ks + qid) * BP + c0]);
                bf[nt][1] = f2tf(Bsb[(ks + qid + 4) * BP + c0]);
            }
            #pragma unroll
            for (int mt = 0; mt < 4; ++mt)
                #pragma unroll
                for (int nt = 0; nt < 4; ++nt)
                    mma_tf32(acc[mt][nt], af[mt], bf[nt]);
        }
        __syncthreads();
    }

    #pragma unroll
    for (int mt = 0; mt < 4; ++mt) {
        #pragma unroll
        for (int nt = 0; nt < 4; ++nt) {
            size_t r  = bm + wm * 64 + mt * 16 + grp;
            size_t c0 = bn + wn * 32 + nt * 8 + 2 * qid;
            *(float2*)&C[r * (size_t)N + c0]       = make_float2(acc[mt][nt][0], acc[mt][nt][1]);
            *(float2*)&C[(r + 8) * (size_t)N + c0] = make_float2(acc[mt][nt][2], acc[mt][nt][3]);
        }
    }
}

// ---------------------------------------------------------------------------
// Fused RoPE + bf16 hi/lo split+pack
// ---------------------------------------------------------------------------
__global__ void rope_split_kernel(const float* __restrict__ src,
                                  unsigned int* __restrict__ dsth,
                                  unsigned int* __restrict__ dstl,
                                  const float* __restrict__ cosb,
                                  const float* __restrict__ sinb,
                                  int nh, int pitch, int total)
{
    int idx = blockIdx.x * blockDim.x + threadIdx.x;
    if (idx >= total) return;
    int cp  = idx & 63;
    int h   = (idx >> 6) % nh;
    int row = idx / (64 * nh);
    int t   = row % TT;

    const float* p = src + (size_t)row * pitch + h * DD;

    float f[2];
    #pragma unroll
    for (int i = 0; i < 2; ++i) {
        int d = 2 * cp + i;
        float x = p[d];
        if (d < 32)
            f[i] = x * cosb[t * RR + d] - p[d + 32] * sinb[t * RR + d];
        else if (d < 64)
            f[i] = x * cosb[t * RR + d] + p[d - 32] * sinb[t * RR + d];
        else
            f[i] = x;
    }
    unsigned int hi, lo;
    split_bf16x2(f[0], f[1], hi, lo);
    size_t o = (size_t)row * (pitch / 2) + h * 64 + cp;
    dsth[o] = hi;
    dstl[o] = lo;
}

// ---------------------------------------------------------------------------
// Two-pass causal attention with threshold gating.
// Pass 1: QK bf16x2 3-term MMA (term-major), direct e-stash write; online m,l.
// Pass 2: exact tile-skip, gate, PV via tf32 MMA.
// ---------------------------------------------------------------------------
constexpr int BQ  = 64;
constexpr int BKT = 64;
constexpr int KP  = 68;
constexpr int SP  = 65;
constexpr int VPITCH = 136;
constexpr int PPITCH = 68;
constexpr int RDP = 17;
constexpr int NKT = TT / BKT;
constexpr int ATT_SMEM_FLOATS =
    4 * BQ * KP + BQ * SP + BQ * VPITCH + BQ * PPITCH + BQ * RDP
    + 2 * NKT * BQ + 4 * BQ + 4;
constexpr int ATT_SMEM_BYTES = ATT_SMEM_FLOATS * 4;

__global__ __launch_bounds__(256, 1) void attn_kernel(
    const float* __restrict__ Vm, const float* __restrict__ gate,
    float* __restrict__ Y)
{
    extern __shared__ float sm[];
    unsigned int* Qhu = (unsigned int*)sm;
    unsigned int* Qlu = Qhu + BQ * KP;
    unsigned int* Khu = Qlu + BQ * KP;
    unsigned int* Klu = Khu + BQ * KP;
    float* Ss       = (float*)(Klu + BQ * KP);
    float* Vs       = Ss + BQ * SP;
    float* Ps       = Vs + BQ * VPITCH;
    float* red      = Ps + BQ * PPITCH;
    float* mn_all   = red + BQ * RDP;
    float* tmax_all = mn_all + NKT * BQ;
    float* m_s      = tmax_all + NKT * BQ;
    float* l_s      = m_s + BQ;
    float* mn_s     = l_s + BQ;
    float* li_s     = mn_s + BQ;
    float* sflag    = li_s + BQ;
    unsigned int* Vsu = (unsigned int*)Vs;
    unsigned int* Psu = (unsigned int*)Ps;

    const int qt = blockIdx.x;
    const int bh = blockIdx.y;
    const int b  = bh / HH;
    const int h  = bh % HH;
    const int q0 = qt * BQ;
    const int tid  = threadIdx.x;
    const int ty   = tid / 16;
    const int tx   = tid % 16;
    const int lane = tid & 31;
    const int w    = tid >> 5;
    const int wm   = w >> 2;
    const int wn   = w & 3;
    const int grp  = lane >> 2;
    const int qid  = lane & 3;

    const float scale = 0.08838834764831845f;
    const float thr = 1.0f / (1.0f + __expf(-gate[h]));

    const unsigned int* Qhg = g_qh + (size_t)(b * TT) * (CC / 2) + h * 64;
    const unsigned int* Qlg = g_ql + (size_t)(b * TT) * (CC / 2) + h * 64;
    const unsigned int* Khg = g_kh + (size_t)(b * TT) * (KVC / 2) + (h / REP) * 64;
    const unsigned int* Klg = g_kl + (size_t)(b * TT) * (KVC / 2) + (h / REP) * 64;
    const float* Vb = Vm + (size_t)(b * TT) * KVC + (h / REP) * DD;
    float* Eb = g_s + ((size_t)bh * TT + q0) * TT;

    for (int e = tid; e < BQ * 64; e += 256) {
        int r = e >> 6, cp = e & 63;
        Qhu[r * KP + cp] = Qhg[(size_t)(q0 + r) * (CC / 2) + cp];
        Qlu[r * KP + cp] = Qlg[(size_t)(q0 + r) * (CC / 2) + cp];
    }
    if (tid < BQ) { m_s[tid] = -1e30f; l_s[tid] = 0.0f; }
    __syncthreads();

    const int m0  = wm * 32;
    const int n0q = wn * 16;

    // ---------------- PASS 1 ----------------
    for (int kt = 0; kt <= qt; ++kt) {
        const int s0 = kt * BKT;

        for (int e = tid; e < BKT * 64; e += 256) {
            int r = e >> 6, cp = e & 63;
            Khu[r * KP + cp] = Khg[(size_t)(s0 + r) * (KVC / 2) + cp];
            Klu[r * KP + cp] = Klg[(size_t)(s0 + r) * (KVC / 2) + cp];
        }
        __syncthreads();

        float sacc[2][2][4];
        #pragma unroll
        for (int mt = 0; mt < 2; ++mt)
            #pragma unroll
            for (int nt = 0; nt < 2; ++nt)
                #pragma unroll
                for (int c = 0; c < 4; ++c) sacc[mt][nt][c] = 0.0f;

        #pragma unroll
        for (int ks = 0; ks < 8; ++ks) {
            const int kp0 = ks * 8;
            unsigned int ah[2][4], al[2][4], bh[2][2], bl[2][2];
            #pragma unroll
            for (int mt = 0; mt < 2; ++mt) {
                int rr = m0 + mt * 16 + grp;
                ah[mt][0] = Qhu[rr * KP + kp0 + qid];
                ah[mt][1] = Qhu[(rr + 8) * KP + kp0 + qid];
                ah[mt][2] = Qhu[rr * KP + kp0 + qid + 4];
                ah[mt][3] = Qhu[(rr + 8) * KP + kp0 + qid + 4];
                al[mt][0] = Qlu[rr * KP + kp0 + qid];
                al[mt][1] = Qlu[(rr + 8) * KP + kp0 + qid];
                al[mt][2] = Qlu[rr * KP + kp0 + qid + 4];
                al[mt][3] = Qlu[(rr + 8) * KP + kp0 + qid + 4];
            }
            #pragma unroll
            for (int nt = 0; nt < 2; ++nt) {
                int cc = n0q + nt * 8 + grp;
                bh[nt][0] = Khu[cc * KP + kp0 + qid];
                bh[nt][1] = Khu[cc * KP + kp0 + qid + 4];
                bl[nt][0] = Klu[cc * KP + kp0 + qid];
                bl[nt][1] = Klu[cc * KP + kp0 + qid + 4];
            }
            // term-major ordering (acc reuse distance 4)
            #pragma unroll
            for (int mt = 0; mt < 2; ++mt)
                #pragma unroll
                for (int nt = 0; nt < 2; ++nt)
                    mma_bf16(sacc[mt][nt], al[mt], bh[nt]);
            #pragma unroll
            for (int mt = 0; mt < 2; ++mt)
                #pragma unroll
                for (int nt = 0; nt < 2; ++nt)
                    mma_bf16(sacc[mt][nt], ah[mt], bl[nt]);
            #pragma unroll
            for (int mt = 0; mt < 2; ++mt)
                #pragma unroll
                for (int nt = 0; nt < 2; ++nt)
                    mma_bf16(sacc[mt][nt], ah[mt], bh[nt]);
        }

        const bool diag = (kt == qt);
        #pragma unroll
        for (int mt = 0; mt < 2; ++mt) {
            #pragma unroll
            for (int nt = 0; nt < 2; ++nt) {
                int rr = m0 + mt * 16 + grp;
                int cc = n0q + nt * 8 + 2 * qid;
                float v0 = sacc[mt][nt][0] * scale;
                float v1 = sacc[mt][nt][1] * scale;
                float v2 = sacc[mt][nt][2] * scale;
                float v3 = sacc[mt][nt][3] * scale;
                if (diag) {
                    if (cc > rr)         v0 = -1e30f;
                    if (cc + 1 > rr)     v1 = -1e30f;
                    if (cc > rr + 8)     v2 = -1e30f;
                    if (cc + 1 > rr + 8) v3 = -1e30f;
                }
                Ss[rr * SP + cc]           = v0;
                Ss[rr * SP + cc + 1]       = v1;
                Ss[(rr + 8) * SP + cc]     = v2;
                Ss[(rr + 8) * SP + cc + 1] = v3;
            }
        }
        __syncthreads();

        #pragma unroll
        for (int i = 0; i < 4; ++i) {
            const int r = ty + 16 * i;
            float pm = -1e30f;
            #pragma unroll
            for (int j = 0; j < 4; ++j)
                pm = fmaxf(pm, Ss[r * SP + tx + 16 * j]);
            red[r * RDP + tx] = pm;
        }
        __syncthreads();

        float mo = 0.0f, mn = 0.0f;
        if (tid < BQ) {
            float tm = red[tid * RDP];
            #pragma unroll
            for (int k = 1; k < 16; ++k) tm = fmaxf(tm, red[tid * RDP + k]);
            mo = m_s[tid];
            mn = fmaxf(mo, tm);
            mn_s[tid] = mn;
            mn_all[kt * BQ + tid] = mn;
            tmax_all[kt * BQ + tid] = tm;
        }
        __syncthreads();

        // e = exp(s - mn_kt): direct stash + partial row sums
        #pragma unroll
        for (int i = 0; i < 4; ++i) {
            const int r = ty + 16 * i;
            const float mr = mn_s[r];
            float ps = 0.0f;
            #pragma unroll
            for (int j = 0; j < 4; ++j) {
                const int c = tx + 16 * j;
                float ei = __expf(Ss[r * SP + c] - mr);
                Eb[(size_t)r * TT + s0 + c] = ei;
                ps += ei;
            }
            red[r * RDP + tx] = ps;
        }
        __syncthreads();

        if (tid < BQ) {
            float ts = 0.0f;
            #pragma unroll
            for (int k = 0; k < 16; ++k) ts += red[tid * RDP + k];
            l_s[tid] = l_s[tid] * __expf(mo - mn) + ts;
            m_s[tid] = mn;
        }
        __syncthreads();
    }

    if (tid < BQ) li_s[tid] = 1.0f / l_s[tid];
    __syncthreads();

    // ---------------- PASS 2: tile-skip + gate + PV ----------------
    float o[2][4][4];
    #pragma unroll
    for (int mt = 0; mt < 2; ++mt)
        #pragma unroll
        for (int nt = 0; nt < 4; ++nt)
            #pragma unroll
            for (int c = 0; c < 4; ++c) o[mt][nt][c] = 0.0f;

    const int n0 = wn * 32;

    for (int kt = 0; kt <= qt; ++kt) {
        const int s0 = kt * BKT;

        if (tid == 0) sflag[0] = 0.0f;
        __syncthreads();
        if (tid < BQ) {
            float pmax = __expf(tmax_all[kt * BQ + tid] - m_s[tid]) * li_s[tid];
            mn_s[tid] = __expf(mn_all[kt * BQ + tid] - m_s[tid]) * li_s[tid];
            if (pmax * 1.00001f >= thr) sflag[0] = 1.0f;
        }
        __syncthreads();
        if (sflag[0] == 0.0f) continue;

        for (int e = tid; e < BKT * DD; e += 256) {
            int r = e >> 7, d = e & 127;
            Vsu[r * VPITCH + d] = f2tf(Vb[(size_t)(s0 + r) * KVC + d]);
        }
        __syncthreads();

        for (int e = tid; e < BQ * BKT; e += 256) {
            int r = e >> 6, c = e & 63;
            float p = Eb[(size_t)r * TT + s0 + c] * mn_s[r];
            if (p < thr) p = 0.0f;
            Psu[r * PPITCH + c] = f2tf(p);
        }
        __syncthreads();

        #pragma unroll
        for (int k = 0; k < BKT; k += 8) {
            unsigned int af[2][4], bf[4][2];
            #pragma unroll
            for (int mt = 0; mt < 2; ++mt) {
                int rr = m0 + mt * 16 + grp;
                af[mt][0] = Psu[rr * PPITCH + k + qid];
                af[mt][1] = Psu[(rr + 8) * PPITCH + k + qid];
                af[mt][2] = Psu[rr * PPITCH + k + qid + 4];
                af[mt][3] = Psu[(rr + 8) * PPITCH + k + qid + 4];
            }
            #pragma unroll
            for (int nt = 0; nt < 4; ++nt) {
                int cc = n0 + nt * 8 + grp;
                bf[nt][0] = Vsu[(k + qid) * VPITCH + cc];
                bf[nt][1] = Vsu[(k + qid + 4) * VPITCH + cc];
            }
            #pragma unroll
            for (int mt = 0; mt < 2; ++mt)
                #pragma unroll
                for (int nt = 0; nt < 4; ++nt)
                    mma_tf32(o[mt][nt], af[mt], bf[nt]);
        }
        __syncthreads();
    }

    #pragma unroll
    for (int mt = 0; mt < 2; ++mt) {
        #pragma unroll
        for (int nt = 0; nt < 4; ++nt) {
            size_t row = (size_t)(b * TT + q0 + m0 + mt * 16 + grp);
            size_t col = h * DD + n0 + nt * 8 + 2 * qid;
            *(float2*)&Y[row * CC + col]       = make_float2(o[mt][nt][0], o[mt][nt][1]);
            *(float2*)&Y[(row + 8) * CC + col] = make_float2(o[mt][nt][2], o[mt][nt][3]);
        }
    }
}

// ---------------------------------------------------------------------------
// Launch — stream-parallel DAG (graph-capture-legal event forks/joins)
// ---------------------------------------------------------------------------
extern "C" void kernel_launch(void* const* d_in, const int* in_sizes, int n_in,
                              void* d_out, int out_size)
{
    const float* x    = (const float*)d_in[0];
    const float* cosb = (const float*)d_in[1];
    const float* sinb = (const float*)d_in[2];
    const float* Wq   = (const float*)d_in[3];
    const float* Wk   = (const float*)d_in[4];
    const float* Wv   = (const float*)d_in[5];
    const float* Wo   = (const float*)d_in[6];
    const float* gate = (const float*)d_in[7];
    float* out = (float*)d_out;

    float *q, *k, *v, *y;
    unsigned int *qh, *ql, *kh, *kl, *xh, *xl, *wqh, *wql, *wkh, *wkl;
    cudaGetSymbolAddress((void**)&q,   g_q);
    cudaGetSymbolAddress((void**)&k,   g_k);
    cudaGetSymbolAddress((void**)&v,   g_v);
    cudaGetSymbolAddress((void**)&y,   g_y);
    cudaGetSymbolAddress((void**)&qh,  g_qh);
    cudaGetSymbolAddress((void**)&ql,  g_ql);
    cudaGetSymbolAddress((void**)&kh,  g_kh);
    cudaGetSymbolAddress((void**)&kl,  g_kl);
    cudaGetSymbolAddress((void**)&xh,  g_xh);
    cudaGetSymbolAddress((void**)&xl,  g_xl);
    cudaGetSymbolAddress((void**)&wqh, g_wqh);
    cudaGetSymbolAddress((void**)&wql, g_wql);
    cudaGetSymbolAddress((void**)&wkh, g_wkh);
    cudaGetSymbolAddress((void**)&wkl, g_wkl);

    static bool init = false;
    static cudaStream_t st1, st2;
    static cudaEvent_t evRoot, evX, evWq, evK, evV;
    if (!init) {
        cudaFuncSetAttribute(attn_kernel,
                             cudaFuncAttributeMaxDynamicSharedMemorySize, ATT_SMEM_BYTES);
        cudaStreamCreateWithFlags(&st1, cudaStreamNonBlocking);
        cudaStreamCreateWithFlags(&st2, cudaStreamNonBlocking);
        cudaEventCreateWithFlags(&evRoot, cudaEventDisableTiming);
        cudaEventCreateWithFlags(&evX,    cudaEventDisableTiming);
        cudaEventCreateWithFlags(&evWq,   cudaEventDisableTiming);
        cudaEventCreateWithFlags(&evK,    cudaEventDisableTiming);
        cudaEventCreateWithFlags(&evV,    cudaEventDisableTiming);
        init = true;
    }

    const int totx = MROWS * (CC / 2);
    const int totq = MROWS * HH * 64;
    const int totk = MROWS * HKVV * 64;

    cudaEventRecord(evRoot, 0);

    // st2: wsplit(Wq) (needed by main's Wq gemm), then Wv projection
    cudaStreamWaitEvent(st2, evRoot, 0);
    wsplit_kernel<<<dim3(CC / 64, CC / 64), 256, 0, st2>>>(Wq, wqh, wql, CC);
    cudaEventRecord(evWq, st2);
    tgemm1_kernel<<<dim3(KVC / 128, MROWS / 128), 256, 0, st2>>>(MROWS, KVC, CC, x, Wv, v);
    cudaEventRecord(evV, st2);

    // main: xsplit (critical path for both q and k gemms)
    xsplit_kernel<<<(totx + 255) / 256, 256>>>(x, xh, xl, totx);
    cudaEventRecord(evX, 0);

    // st1: Wk chain (wsplit -> gemm -> rope_split)
    cudaStreamWaitEvent(st1, evX, 0);
    wsplit_kernel<<<dim3(CC / 64, KVC / 64), 256, 0, st1>>>(Wk, wkh, wkl, KVC);
    tgemm3p_kernel<<<dim3(KVC / 128, MROWS / 128), 256, 0, st1>>>(
        MROWS, KVC, CC, xh, xl, wkh, wkl, k);
    rope_split_kernel<<<(totk + 255) / 256, 256, 0, st1>>>(
        k, kh, kl, cosb, sinb, HKVV, KVC, totk);
    cudaEventRecord(evK, st1);

    // main: Wq chain
    cudaStreamWaitEvent(0, evWq, 0);
    tgemm3p_kernel<<<dim3(CC / 128, MROWS / 128), 256>>>(
        MROWS, CC, CC, xh, xl, wqh, wql, q);
    rope_split_kernel<<<(totq + 255) / 256, 256>>>(q, qh, ql, cosb, sinb, HH, CC, totq);

    // join: attention needs qh/ql (main), kh/kl (st1), v (st2)
    cudaStreamWaitEvent(0, evK, 0);
    cudaStreamWaitEvent(0, evV, 0);
    attn_kernel<<<dim3(TT / BQ, BB * HH), 256, ATT_SMEM_BYTES>>>(v, gate, y);

    // output projection
    tgemm1_kernel<<<dim3(CC / 128, MROWS / 128), 256>>>(MROWS, CC, CC, y, Wo, out);
}

// round 17
// speedup vs baseline: 1.0954x; 1.0410x over previous
#include <cuda_runtime.h>
#include <cuda_bf16.h>
#include <cstdint>
#include <stdint.h>
#include <math.h>

// Problem constants
constexpr int BB  = 2;
constexpr int TT  = 2048;
constexpr int CC  = 2048;
constexpr int HH  = 16;
constexpr int HKVV = 4;
constexpr int DD  = 128;
constexpr int RR  = 64;
constexpr int KVC = HKVV * DD;      // 512
constexpr int REP = HH / HKVV;      // 4
constexpr int MROWS = BB * TT;      // 4096

// ---------------------------------------------------------------------------
// Scratch (static __device__ arrays; no allocations allowed)
// ---------------------------------------------------------------------------
__device__ float g_v[(size_t)MROWS * KVC];
__device__ float g_y[(size_t)MROWS * CC];
__device__ float g_s[(size_t)BB * HH * TT * TT];        // e stash
__device__ unsigned int g_qh[(size_t)MROWS * CC / 2];   // roped q bf16 hi pairs
__device__ unsigned int g_ql[(size_t)MROWS * CC / 2];
__device__ unsigned int g_kh[(size_t)MROWS * KVC / 2];
__device__ unsigned int g_kl[(size_t)MROWS * KVC / 2];
__device__ unsigned int g_xh[(size_t)MROWS * CC / 2];   // x bf16 hi pairs [M][K/2]
__device__ unsigned int g_xl[(size_t)MROWS * CC / 2];
__device__ unsigned int g_wqh[(size_t)CC * CC / 2];     // Wq^T packed [N][K/2]
__device__ unsigned int g_wql[(size_t)CC * CC / 2];
__device__ unsigned int g_wkh[(size_t)KVC * CC / 2];    // Wk^T packed [N][K/2]
__device__ unsigned int g_wkl[(size_t)KVC * CC / 2];

// ---------------------------------------------------------------------------
// helpers
// ---------------------------------------------------------------------------
__device__ __forceinline__ unsigned int f2tf(float f) {
    unsigned int r;
    asm("cvt.rna.tf32.f32 %0, %1;" : "=r"(r) : "f"(f));
    return r;
}

__device__ __forceinline__ void split_bf16x2(float f0, float f1,
                                             unsigned int& hi, unsigned int& lo) {
    __nv_bfloat162 h = __floats2bfloat162_rn(f0, f1);
    float2 hf = __bfloat1622float2(h);
    __nv_bfloat162 l = __floats2bfloat162_rn(f0 - hf.x, f1 - hf.y);
    hi = *reinterpret_cast<unsigned int*>(&h);
    lo = *reinterpret_cast<unsigned int*>(&l);
}

__device__ __forceinline__ void cp16(void* smem_ptr, const void* gptr) {
    unsigned int s = (unsigned int)__cvta_generic_to_shared(smem_ptr);
    asm volatile("cp.async.cg.shared.global [%0], [%1], 16;" :: "r"(s), "l"(gptr));
}

__device__ __forceinline__ void mma_tf32(float* d, const unsigned int* a, const unsigned int* b) {
    asm volatile(
        "mma.sync.aligned.m16n8k8.row.col.f32.tf32.tf32.f32 "
        "{%0,%1,%2,%3}, {%4,%5,%6,%7}, {%8,%9}, {%0,%1,%2,%3};"
        : "+f"(d[0]), "+f"(d[1]), "+f"(d[2]), "+f"(d[3])
        : "r"(a[0]), "r"(a[1]), "r"(a[2]), "r"(a[3]), "r"(b[0]), "r"(b[1]));
}

__device__ __forceinline__ void mma_bf16(float* d, const unsigned int* a, const unsigned int* b) {
    asm volatile(
        "mma.sync.aligned.m16n8k16.row.col.f32.bf16.bf16.f32 "
        "{%0,%1,%2,%3}, {%4,%5,%6,%7}, {%8,%9}, {%0,%1,%2,%3};"
        : "+f"(d[0]), "+f"(d[1]), "+f"(d[2]), "+f"(d[3])
        : "r"(a[0]), "r"(a[1]), "r"(a[2]), "r"(a[3]), "r"(b[0]), "r"(b[1]));
}

// ---------------------------------------------------------------------------
// Pre-split kernels
// ---------------------------------------------------------------------------
__global__ void xsplit_kernel(const float* __restrict__ X,
                              unsigned int* __restrict__ Xh,
                              unsigned int* __restrict__ Xl, int total)
{
    int i = blockIdx.x * blockDim.x + threadIdx.x;
    if (i >= total) return;
    unsigned int hi, lo;
    split_bf16x2(X[2 * (size_t)i], X[2 * (size_t)i + 1], hi, lo);
    Xh[i] = hi;
    Xl[i] = lo;
}

// W [K=2048][N] row-major -> Wt hi/lo packed [N][K/2] (transpose + split)
__global__ __launch_bounds__(256) void wsplit_kernel(
    const float* __restrict__ W,
    unsigned int* __restrict__ Th, unsigned int* __restrict__ Tl, int N)
{
    __shared__ float t[64][65];
    const int k0 = blockIdx.x * 64, n0 = blockIdx.y * 64;
    const int tid = threadIdx.x;
    const int KU = CC / 2;
    for (int i = tid; i < 64 * 64; i += 256) {
        int r = i >> 6, c = i & 63;
        t[r][c] = W[(size_t)(k0 + r) * N + n0 + c];
    }
    __syncthreads();
    for (int i = tid; i < 64 * 32; i += 256) {
        int n = i >> 5, kp = i & 31;
        unsigned int hi, lo;
        split_bf16x2(t[2 * kp][n], t[2 * kp + 1][n], hi, lo);
        size_t o = (size_t)(n0 + n) * KU + (k0 >> 1) + kp;
        Th[o] = hi;
        Tl[o] = lo;
    }
}

// ---------------------------------------------------------------------------
// Packed bf16x2 3-term GEMM with fused RoPE+split epilogue.
// C[M,N] = A @ Wt^T, then per 128-wide tile (= one head): rope first RR dims,
// bf16 hi/lo split, write packed [M][N/2] outputs directly. No fp32 C.
// __launch_bounds__(256,2): 2 CTAs/SM for HMMA latency hiding.
// ---------------------------------------------------------------------------
constexpr int GP = 12;                 // uint pitch
constexpr int G_STAGE = 128 * GP;      // uints per array per stage
constexpr int EPIP = 132;              // epilogue staging float pitch

__global__ __launch_bounds__(256, 2) void tgemm3r_kernel(
    int M, int N, int K,
    const unsigned int* __restrict__ Ah, const unsigned int* __restrict__ Al,
    const unsigned int* __restrict__ Bh, const unsigned int* __restrict__ Bl,
    const float* __restrict__ cosb, const float* __restrict__ sinb,
    unsigned int* __restrict__ OUTh, unsigned int* __restrict__ OUTl)
{
    __shared__ unsigned int us[2 * 4 * G_STAGE];   // 49152 B

    const int tid  = threadIdx.x;
    const int lane = tid & 31;
    const int w    = tid >> 5;
    const int wm   = w >> 2;
    const int wn   = w & 3;
    const int grp  = lane >> 2;
    const int qid  = lane & 3;

    const size_t bm = (size_t)blockIdx.y * 128;
    const size_t bn = (size_t)blockIdx.x * 128;
    const int KU = K >> 1;
    const int OUTP = N >> 1;

    float acc[4][4][4];
    #pragma unroll
    for (int i = 0; i < 4; ++i)
        #pragma unroll
        for (int j = 0; j < 4; ++j)
            #pragma unroll
            for (int c = 0; c < 4; ++c) acc[i][j][c] = 0.0f;

    const unsigned int* srcs[4] = {Ah, Al, Bh, Bl};
    const int row  = tid >> 1;
    const int half = tid & 1;

    auto load_stage = [&](int ku0, int buf) {
        #pragma unroll
        for (int t = 0; t < 4; ++t) {
            const size_t row0 = (t < 2) ? bm : bn;
            unsigned int* dst = us + (buf * 4 + t) * G_STAGE;
            cp16(&dst[row * GP + half * 4],
                 srcs[t] + (row0 + row) * KU + ku0 + half * 4);
        }
        asm volatile("cp.async.commit_group;");
    };

    load_stage(0, 0);

    const int nst = K / 16;
    for (int s = 0; s < nst; ++s) {
        asm volatile("cp.async.wait_group 0;");
        __syncthreads();
        if (s + 1 < nst) load_stage((s + 1) * 8, (s + 1) & 1);

        const unsigned int* base = us + (s & 1) * 4 * G_STAGE;
        const unsigned int* Ahs = base;
        const unsigned int* Als = base + G_STAGE;
        const unsigned int* Bhs = base + 2 * G_STAGE;
        const unsigned int* Bls = base + 3 * G_STAGE;

        unsigned int ah[4][4], al[4][4], bh[4][2], bl[4][2];
        #pragma unroll
        for (int mt = 0; mt < 4; ++mt) {
            int r0 = wm * 64 + mt * 16 + grp;
            ah[mt][0] = Ahs[r0 * GP + qid];
            ah[mt][1] = Ahs[(r0 + 8) * GP + qid];
            ah[mt][2] = Ahs[r0 * GP + qid + 4];
            ah[mt][3] = Ahs[(r0 + 8) * GP + qid + 4];
            al[mt][0] = Als[r0 * GP + qid];
            al[mt][1] = Als[(r0 + 8) * GP + qid];
            al[mt][2] = Als[r0 * GP + qid + 4];
            al[mt][3] = Als[(r0 + 8) * GP + qid + 4];
        }
        #pragma unroll
        for (int nt = 0; nt < 4; ++nt) {
            int cc = wn * 32 + nt * 8 + grp;
            bh[nt][0] = Bhs[cc * GP + qid];
            bh[nt][1] = Bhs[cc * GP + qid + 4];
            bl[nt][0] = Bls[cc * GP + qid];
            bl[nt][1] = Bls[cc * GP + qid + 4];
        }
        // term-major: same-acc reuse distance = 16 MMAs
        #pragma unroll
        for (int mt = 0; mt < 4; ++mt)
            #pragma unroll
            for (int nt = 0; nt < 4; ++nt)
                mma_bf16(acc[mt][nt], al[mt], bh[nt]);
        #pragma unroll
        for (int mt = 0; mt < 4; ++mt)
            #pragma unroll
            for (int nt = 0; nt < 4; ++nt)
                mma_bf16(acc[mt][nt], ah[mt], bl[nt]);
        #pragma unroll
        for (int mt = 0; mt < 4; ++mt)
            #pragma unroll
            for (int nt = 0; nt < 4; ++nt)
                mma_bf16(acc[mt][nt], ah[mt], bh[nt]);
        __syncthreads();
    }

    // ---- Fused RoPE + split epilogue (two 64-row halves, staged in smem) ----
    float* stg = (float*)us;   // [64][EPIP] floats = 33 KB
    #pragma unroll
    for (int hfi = 0; hfi < 2; ++hfi) {
        if (wm == hfi) {
            #pragma unroll
            for (int mt = 0; mt < 4; ++mt) {
                #pragma unroll
                for (int nt = 0; nt < 4; ++nt) {
                    int rr = mt * 16 + grp;
                    int cc = wn * 32 + nt * 8 + 2 * qid;
                    stg[rr * EPIP + cc]           = acc[mt][nt][0];
                    stg[rr * EPIP + cc + 1]       = acc[mt][nt][1];
                    stg[(rr + 8) * EPIP + cc]     = acc[mt][nt][2];
                    stg[(rr + 8) * EPIP + cc + 1] = acc[mt][nt][3];
                }
            }
        }
        __syncthreads();

        for (int e = tid; e < 64 * 64; e += 256) {
            int r  = e >> 6, cp = e & 63;
            size_t rowg = bm + hfi * 64 + r;
            int t = (int)(rowg & (TT - 1));
            int d0 = 2 * cp;
            float f0, f1;
            if (d0 < 32) {
                f0 = stg[r * EPIP + d0]     * cosb[t * RR + d0]
                   - stg[r * EPIP + d0 + 32] * sinb[t * RR + d0];
                f1 = stg[r * EPIP + d0 + 1] * cosb[t * RR + d0 + 1]
                   - stg[r * EPIP + d0 + 33] * sinb[t * RR + d0 + 1];
            } else if (d0 < 64) {
                f0 = stg[r * EPIP + d0]     * cosb[t * RR + d0]
                   + stg[r * EPIP + d0 - 32] * sinb[t * RR + d0];
                f1 = stg[r * EPIP + d0 + 1] * cosb[t * RR + d0 + 1]
                   + stg[r * EPIP + d0 - 31] * sinb[t * RR + d0 + 1];
            } else {
                f0 = stg[r * EPIP + d0];
                f1 = stg[r * EPIP + d0 + 1];
            }
            unsigned int hi, lo;
            split_bf16x2(f0, f1, hi, lo);
            size_t o = rowg * OUTP + (bn >> 1) + cp;
            OUTh[o] = hi;
            OUTl[o] = lo;
        }
        __syncthreads();
    }
}

// ---------------------------------------------------------------------------
// tf32 mma.sync GEMM (single tf32 — smooth paths Wv/Wo)
// ---------------------------------------------------------------------------
__global__ __launch_bounds__(256) void tgemm1_kernel(
    int M, int N, int K,
    const float* __restrict__ A, const float* __restrict__ B,
    float* __restrict__ C)
{
    constexpr int BM = 128, BN = 128, BK = 16, AP = 20, BP = 136;
    __shared__ float As[2][BM * AP];
    __shared__ float Bs[2][BK * BP];

    const int tid  = threadIdx.x;
    const int lane = tid & 31;
    const int w    = tid >> 5;
    const int wm   = w >> 2;
    const int wn   = w & 3;
    const int grp  = lane >> 2;
    const int qid  = lane & 3;

    const size_t bm = (size_t)blockIdx.y * BM;
    const size_t bn = (size_t)blockIdx.x * BN;

    float acc[4][4][4];
    #pragma unroll
    for (int i = 0; i < 4; ++i)
        #pragma unroll
        for (int j = 0; j < 4; ++j)
            #pragma unroll
            for (int c = 0; c < 4; ++c) acc[i][j][c] = 0.0f;

    auto load_stage = [&](int k0, int buf) {
        #pragma unroll
        for (int c = 0; c < 2; ++c) {
            int idx = tid + c * 256;
            int row = idx >> 2, col = (idx & 3) * 4;
            cp16(&As[buf][row * AP + col], &A[(bm + row) * (size_t)K + k0 + col]);
        }
        #pragma unroll
        for (int c = 0; c < 2; ++c) {
            int idx = tid + c * 256;
            int row = idx >> 5, col = (idx & 31) * 4;
            cp16(&Bs[buf][row * BP + col], &B[(size_t)(k0 + row) * N + bn + col]);
        }
    };

    load_stage(0, 0);
    asm volatile("cp.async.commit_group;");

    const int nst = K / BK;
    for (int s = 0; s < nst; ++s) {
        asm volatile("cp.async.wait_group 0;");
        __syncthreads();
        const int cur = s & 1;
        if (s + 1 < nst) {
            load_stage((s + 1) * BK, cur ^ 1);
            asm volatile("cp.async.commit_group;");
        }
        const float* Asb = As[cur];
        const float* Bsb = Bs[cur];
        #pragma unroll
        for (int ks = 0; ks < BK; ks += 8) {
            unsigned int af[4][4], bf[4][2];
            #pragma unroll
            for (int mt = 0; mt < 4; ++mt) {
                int r0 = wm * 64 + mt * 16 + grp;
                af[mt][0] = f2tf(Asb[r0 * AP + ks + qid]);
                af[mt][1] = f2tf(Asb[(r0 + 8) * AP + ks + qid]);
                af[mt][2] = f2tf(Asb[r0 * AP + ks + qid + 4]);
                af[mt][3] = f2tf(Asb[(r0 + 8) * AP + ks + qid + 4]);
            }
            #pragma unroll
            for (int nt = 0; nt < 4; ++nt) {
                int c0 = wn * 32 + nt * 8 + grp;
                bf[nt][0] = f2tf(Bsb[(ks + qid) * BP + c0]);
                bf[nt][1] = f2tf(Bsb[(ks + qid + 4) * BP + c0]);
            }
            #pragma unroll
            for (int mt = 0; mt < 4; ++mt)
                #pragma unroll
                for (int nt = 0; nt < 4; ++nt)
                    mma_tf32(acc[mt][nt], af[mt], bf[nt]);
        }
        __syncthreads();
    }

    #pragma unroll
    for (int mt = 0; mt < 4; ++mt) {
        #pragma unroll
        for (int nt = 0; nt < 4; ++nt) {
            size_t r  = bm + wm * 64 + mt * 16 + grp;
            size_t c0 = bn + wn * 32 + nt * 8 + 2 * qid;
            *(float2*)&C[r * (size_t)N + c0]       = make_float2(acc[mt][nt][0], acc[mt][nt][1]);
            *(float2*)&C[(r + 8) * (size_t)N + c0] = make_float2(acc[mt][nt][2], acc[mt][nt][3]);
        }
    }
}

// ---------------------------------------------------------------------------
// Two-pass causal attention with threshold gating (qt reversed for balance).
// ---------------------------------------------------------------------------
constexpr int BQ  = 64;
constexpr int BKT = 64;
constexpr int KP  = 68;
constexpr int SP  = 65;
constexpr int VPITCH = 136;
constexpr int PPITCH = 68;
constexpr int RDP = 17;
constexpr int NKT = TT / BKT;
constexpr int ATT_SMEM_FLOATS =
    4 * BQ * KP + BQ * SP + BQ * VPITCH + BQ * PPITCH + BQ * RDP
    + 2 * NKT * BQ + 4 * BQ + 4;
constexpr int ATT_SMEM_BYTES = ATT_SMEM_FLOATS * 4;

__global__ __launch_bounds__(256, 1) void attn_kernel(
    const float* __restrict__ Vm, const float* __restrict__ gate,
    float* __restrict__ Y)
{
    extern __shared__ float sm[];
    unsigned int* Qhu = (unsigned int*)sm;
    unsigned int* Qlu = Qhu + BQ * KP;
    unsigned int* Khu = Qlu + BQ * KP;
    unsigned int* Klu = Khu + BQ * KP;
    float* Ss       = (float*)(Klu + BQ * KP);
    float* Vs       = Ss + BQ * SP;
    float* Ps       = Vs + BQ * VPITCH;
    float* red      = Ps + BQ * PPITCH;
    float* mn_all   = red + BQ * RDP;
    float* tmax_all = mn_all + NKT * BQ;
    float* m_s      = tmax_all + NKT * BQ;
    float* l_s      = m_s + BQ;
    float* mn_s     = l_s + BQ;
    float* li_s     = mn_s + BQ;
    float* sflag    = li_s + BQ;
    unsigned int* Vsu = (unsigned int*)Vs;
    unsigned int* Psu = (unsigned int*)Ps;

    const int qt = gridDim.x - 1 - blockIdx.x;   // heavy blocks first
    const int bh = blockIdx.y;
    const int b  = bh / HH;
    const int h  = bh % HH;
    const int q0 = qt * BQ;
    const int tid  = threadIdx.x;
    const int ty   = tid / 16;
    const int tx   = tid % 16;
    const int lane = tid & 31;
    const int w    = tid >> 5;
    const int wm   = w >> 2;
    const int wn   = w & 3;
    const int grp  = lane >> 2;
    const int qid  = lane & 3;

    const float scale = 0.08838834764831845f;
    const float thr = 1.0f / (1.0f + __expf(-gate[h]));

    const unsigned int* Qhg = g_qh + (size_t)(b * TT) * (CC / 2) + h * 64;
    const unsigned int* Qlg = g_ql + (size_t)(b * TT) * (CC / 2) + h * 64;
    const unsigned int* Khg = g_kh + (size_t)(b * TT) * (KVC / 2) + (h / REP) * 64;
    const unsigned int* Klg = g_kl + (size_t)(b * TT) * (KVC / 2) + (h / REP) * 64;
    const float* Vb = Vm + (size_t)(b * TT) * KVC + (h / REP) * DD;
    float* Eb = g_s + ((size_t)bh * TT + q0) * TT;

    for (int e = tid; e < BQ * 64; e += 256) {
        int r = e >> 6, cp = e & 63;
        Qhu[r * KP + cp] = Qhg[(size_t)(q0 + r) * (CC / 2) + cp];
        Qlu[r * KP + cp] = Qlg[(size_t)(q0 + r) * (CC / 2) + cp];
    }
    if (tid < BQ) { m_s[tid] = -1e30f; l_s[tid] = 0.0f; }
    __syncthreads();

    const int m0  = wm * 32;
    const int n0q = wn * 16;

    // ---------------- PASS 1 ----------------
    for (int kt = 0; kt <= qt; ++kt) {
        const int s0 = kt * BKT;

        for (int e = tid; e < BKT * 64; e += 256) {
            int r = e >> 6, cp = e & 63;
            Khu[r * KP + cp] = Khg[(size_t)(s0 + r) * (KVC / 2) + cp];
            Klu[r * KP + cp] = Klg[(size_t)(s0 + r) * (KVC / 2) + cp];
        }
        __syncthreads();

        float sacc[2][2][4];
        #pragma unroll
        for (int mt = 0; mt < 2; ++mt)
            #pragma unroll
            for (int nt = 0; nt < 2; ++nt)
                #pragma unroll
                for (int c = 0; c < 4; ++c) sacc[mt][nt][c] = 0.0f;

        #pragma unroll
        for (int ks = 0; ks < 8; ++ks) {
            const int kp0 = ks * 8;
            unsigned int ah[2][4], al[2][4], bh[2][2], bl[2][2];
            #pragma unroll
            for (int mt = 0; mt < 2; ++mt) {
                int rr = m0 + mt * 16 + grp;
                ah[mt][0] = Qhu[rr * KP + kp0 + qid];
                ah[mt][1] = Qhu[(rr + 8) * KP + kp0 + qid];
                ah[mt][2] = Qhu[rr * KP + kp0 + qid + 4];
                ah[mt][3] = Qhu[(rr + 8) * KP + kp0 + qid + 4];
                al[mt][0] = Qlu[rr * KP + kp0 + qid];
                al[mt][1] = Qlu[(rr + 8) * KP + kp0 + qid];
                al[mt][2] = Qlu[rr * KP + kp0 + qid + 4];
                al[mt][3] = Qlu[(rr + 8) * KP + kp0 + qid + 4];
            }
            #pragma unroll
            for (int nt = 0; nt < 2; ++nt) {
                int cc = n0q + nt * 8 + grp;
                bh[nt][0] = Khu[cc * KP + kp0 + qid];
                bh[nt][1] = Khu[cc * KP + kp0 + qid + 4];
                bl[nt][0] = Klu[cc * KP + kp0 + qid];
                bl[nt][1] = Klu[cc * KP + kp0 + qid + 4];
            }
            #pragma unroll
            for (int mt = 0; mt < 2; ++mt)
                #pragma unroll
                for (int nt = 0; nt < 2; ++nt)
                    mma_bf16(sacc[mt][nt], al[mt], bh[nt]);
            #pragma unroll
            for (int mt = 0; mt < 2; ++mt)
                #pragma unroll
                for (int nt = 0; nt < 2; ++nt)
                    mma_bf16(sacc[mt][nt], ah[mt], bl[nt]);
            #pragma unroll
            for (int mt = 0; mt < 2; ++mt)
                #pragma unroll
                for (int nt = 0; nt < 2; ++nt)
                    mma_bf16(sacc[mt][nt], ah[mt], bh[nt]);
        }

        const bool diag = (kt == qt);
        #pragma unroll
        for (int mt = 0; mt < 2; ++mt) {
            #pragma unroll
            for (int nt = 0; nt < 2; ++nt) {
                int rr = m0 + mt * 16 + grp;
                int cc = n0q + nt * 8 + 2 * qid;
                float v0 = sacc[mt][nt][0] * scale;
                float v1 = sacc[mt][nt][1] * scale;
                float v2 = sacc[mt][nt][2] * scale;
                float v3 = sacc[mt][nt][3] * scale;
                if (diag) {
                    if (cc > rr)         v0 = -1e30f;
                    if (cc + 1 > rr)     v1 = -1e30f;
                    if (cc > rr + 8)     v2 = -1e30f;
                    if (cc + 1 > rr + 8) v3 = -1e30f;
                }
                Ss[rr * SP + cc]           = v0;
                Ss[rr * SP + cc + 1]       = v1;
                Ss[(rr + 8) * SP + cc]     = v2;
                Ss[(rr + 8) * SP + cc + 1] = v3;
            }
        }
        __syncthreads();

        #pragma unroll
        for (int i = 0; i < 4; ++i) {
            const int r = ty + 16 * i;
            float pm = -1e30f;
            #pragma unroll
            for (int j = 0; j < 4; ++j)
                pm = fmaxf(pm, Ss[r * SP + tx + 16 * j]);
            red[r * RDP + tx] = pm;
        }
        __syncthreads();

        float mo = 0.0f, mn = 0.0f;
        if (tid < BQ) {
            float tm = red[tid * RDP];
            #pragma unroll
            for (int k = 1; k < 16; ++k) tm = fmaxf(tm, red[tid * RDP + k]);
            mo = m_s[tid];
            mn = fmaxf(mo, tm);
            mn_s[tid] = mn;
            mn_all[kt * BQ + tid] = mn;
            tmax_all[kt * BQ + tid] = tm;
        }
        __syncthreads();

        #pragma unroll
        for (int i = 0; i < 4; ++i) {
            const int r = ty + 16 * i;
            const float mr = mn_s[r];
            float ps = 0.0f;
            #pragma unroll
            for (int j = 0; j < 4; ++j) {
                const int c = tx + 16 * j;
                float ei = __expf(Ss[r * SP + c] - mr);
                Eb[(size_t)r * TT + s0 + c] = ei;
                ps += ei;
            }
            red[r * RDP + tx] = ps;
        }
        __syncthreads();

        if (tid < BQ) {
            float ts = 0.0f;
            #pragma unroll
            for (int k = 0; k < 16; ++k) ts += red[tid * RDP + k];
            l_s[tid] = l_s[tid] * __expf(mo - mn) + ts;
            m_s[tid] = mn;
        }
        __syncthreads();
    }

    if (tid < BQ) li_s[tid] = 1.0f / l_s[tid];
    __syncthreads();

    // ---------------- PASS 2: tile-skip + gate + PV ----------------
    float o[2][4][4];
    #pragma unroll
    for (int mt = 0; mt < 2; ++mt)
        #pragma unroll
        for (int nt = 0; nt < 4; ++nt)
            #pragma unroll
            for (int c = 0; c < 4; ++c) o[mt][nt][c] = 0.0f;

    const int n0 = wn * 32;

    for (int kt = 0; kt <= qt; ++kt) {
        const int s0 = kt * BKT;

        if (tid == 0) sflag[0] = 0.0f;
        __syncthreads();
        if (tid < BQ) {
            float pmax = __expf(tmax_all[kt * BQ + tid] - m_s[tid]) * li_s[tid];
            mn_s[tid] = __expf(mn_all[kt * BQ + tid] - m_s[tid]) * li_s[tid];
            if (pmax * 1.00001f >= thr) sflag[0] = 1.0f;
        }
        __syncthreads();
        if (sflag[0] == 0.0f) continue;

        for (int e = tid; e < BKT * DD; e += 256) {
            int r = e >> 7, d = e & 127;
            Vsu[r * VPITCH + d] = f2tf(Vb[(size_t)(s0 + r) * KVC + d]);
        }
        __syncthreads();

        for (int e = tid; e < BQ * BKT; e += 256) {
            int r = e >> 6, c = e & 63;
            float p = Eb[(size_t)r * TT + s0 + c] * mn_s[r];
            if (p < thr) p = 0.0f;
            Psu[r * PPITCH + c] = f2tf(p);
        }
        __syncthreads();

        #pragma unroll
        for (int k = 0; k < BKT; k += 8) {
            unsigned int af[2][4], bf[4][2];
            #pragma unroll
            for (int mt = 0; mt < 2; ++mt) {
                int rr = m0 + mt * 16 + grp;
                af[mt][0] = Psu[rr * PPITCH + k + qid];
                af[mt][1] = Psu[(rr + 8) * PPITCH + k + qid];
                af[mt][2] = Psu[rr * PPITCH + k + qid + 4];
                af[mt][3] = Psu[(rr + 8) * PPITCH + k + qid + 4];
            }
            #pragma unroll
            for (int nt = 0; nt < 4; ++nt) {
                int cc = n0 + nt * 8 + grp;
                bf[nt][0] = Vsu[(k + qid) * VPITCH + cc];
                bf[nt][1] = Vsu[(k + qid + 4) * VPITCH + cc];
            }
            #pragma unroll
            for (int mt = 0; mt < 2; ++mt)
                #pragma unroll
                for (int nt = 0; nt < 4; ++nt)
                    mma_tf32(o[mt][nt], af[mt], bf[nt]);
        }
        __syncthreads();
    }

    #pragma unroll
    for (int mt = 0; mt < 2; ++mt) {
        #pragma unroll
        for (int nt = 0; nt < 4; ++nt) {
            size_t row = (size_t)(b * TT + q0 + m0 + mt * 16 + grp);
            size_t col = h * DD + n0 + nt * 8 + 2 * qid;
            *(float2*)&Y[row * CC + col]       = make_float2(o[mt][nt][0], o[mt][nt][1]);
            *(float2*)&Y[(row + 8) * CC + col] = make_float2(o[mt][nt][2], o[mt][nt][3]);
        }
    }
}

// ---------------------------------------------------------------------------
// Launch — stream-parallel DAG
// ---------------------------------------------------------------------------
extern "C" void kernel_launch(void* const* d_in, const int* in_sizes, int n_in,
                              void* d_out, int out_size)
{
    const float* x    = (const float*)d_in[0];
    const float* cosb = (const float*)d_in[1];
    const float* sinb = (const float*)d_in[2];
    const float* Wq   = (const float*)d_in[3];
    const float* Wk   = (const float*)d_in[4];
    const float* Wv   = (const float*)d_in[5];
    const float* Wo   = (const float*)d_in[6];
    const float* gate = (const float*)d_in[7];
    float* out = (float*)d_out;

    float *v, *y;
    unsigned int *qh, *ql, *kh, *kl, *xh, *xl, *wqh, *wql, *wkh, *wkl;
    cudaGetSymbolAddress((void**)&v,   g_v);
    cudaGetSymbolAddress((void**)&y,   g_y);
    cudaGetSymbolAddress((void**)&qh,  g_qh);
    cudaGetSymbolAddress((void**)&ql,  g_ql);
    cudaGetSymbolAddress((void**)&kh,  g_kh);
    cudaGetSymbolAddress((void**)&kl,  g_kl);
    cudaGetSymbolAddress((void**)&xh,  g_xh);
    cudaGetSymbolAddress((void**)&xl,  g_xl);
    cudaGetSymbolAddress((void**)&wqh, g_wqh);
    cudaGetSymbolAddress((void**)&wql, g_wql);
    cudaGetSymbolAddress((void**)&wkh, g_wkh);
    cudaGetSymbolAddress((void**)&wkl, g_wkl);

    static bool init = false;
    static cudaStream_t st1, st2;
    static cudaEvent_t evRoot, evX, evWq, evK, evV;
    if (!init) {
        cudaFuncSetAttribute(attn_kernel,
                             cudaFuncAttributeMaxDynamicSharedMemorySize, ATT_SMEM_BYTES);
        cudaStreamCreateWithFlags(&st1, cudaStreamNonBlocking);
        cudaStreamCreateWithFlags(&st2, cudaStreamNonBlocking);
        cudaEventCreateWithFlags(&evRoot, cudaEventDisableTiming);
        cudaEventCreateWithFlags(&evX,    cudaEventDisableTiming);
        cudaEventCreateWithFlags(&evWq,   cudaEventDisableTiming);
        cudaEventCreateWithFlags(&evK,    cudaEventDisableTiming);
        cudaEventCreateWithFlags(&evV,    cudaEventDisableTiming);
        init = true;
    }

    const int totx = MROWS * (CC / 2);

    cudaEventRecord(evRoot, 0);

    // st2: wsplit(Wq) (needed by main's Wq gemm), then Wv projection
    cudaStreamWaitEvent(st2, evRoot, 0);
    wsplit_kernel<<<dim3(CC / 64, CC / 64), 256, 0, st2>>>(Wq, wqh, wql, CC);
    cudaEventRecord(evWq, st2);
    tgemm1_kernel<<<dim3(KVC / 128, MROWS / 128), 256, 0, st2>>>(MROWS, KVC, CC, x, Wv, v);
    cudaEventRecord(evV, st2);

    // main: xsplit (critical path for both q and k gemms)
    xsplit_kernel<<<(totx + 255) / 256, 256>>>(x, xh, xl, totx);
    cudaEventRecord(evX, 0);

    // st1: Wk chain (wsplit -> fused gemm+rope+split)
    cudaStreamWaitEvent(st1, evX, 0);
    wsplit_kernel<<<dim3(CC / 64, KVC / 64), 256, 0, st1>>>(Wk, wkh, wkl, KVC);
    tgemm3r_kernel<<<dim3(KVC / 128, MROWS / 128), 256, 0, st1>>>(
        MROWS, KVC, CC, xh, xl, wkh, wkl, cosb, sinb, kh, kl);
    cudaEventRecord(evK, st1);

    // main: Wq chain (fused gemm+rope+split)
    cudaStreamWaitEvent(0, evWq, 0);
    tgemm3r_kernel<<<dim3(CC / 128, MROWS / 128), 256>>>(
        MROWS, CC, CC, xh, xl, wqh, wql, cosb, sinb, qh, ql);

    // join: attention needs qh/ql (main), kh/kl (st1), v (st2)
    cudaStreamWaitEvent(0, evK, 0);
    cudaStreamWaitEvent(0, evV, 0);
    attn_kernel<<<dim3(TT / BQ, BB * HH), 256, ATT_SMEM_BYTES>>>(v, gate, y);

    // output projection
    tgemm1_kernel<<<dim3(CC / 128, MROWS / 128), 256>>>(MROWS, CC, CC, y, Wo, out);
}